// round 11
// baseline (speedup 1.0000x reference)
#include <cuda_runtime.h>
#include <cuda_bf16.h>
#include <stdint.h>
#include <math.h>

#define NTOK 2048
#define DIM  2048
#define NEXP 64
#define TOPK 8
#define FFN  768
#define CAP  512

// ---------------- device scratch ----------------
__device__ int   g_counts[NEXP];
__device__ int   g_tok[NEXP * CAP];
__device__ float g_score[NEXP * CAP];
__device__ int   g_loc[NTOK * TOPK];
__device__ __align__(16) __nv_bfloat16 g_xhi[(size_t)NTOK * DIM];
__device__ __align__(16) __nv_bfloat16 g_xlo[(size_t)NTOK * DIM];
__device__ __align__(16) __nv_bfloat16 g_Hhi[(size_t)NEXP * CAP * FFN];
__device__ __align__(16) __nv_bfloat16 g_Hlo[(size_t)NEXP * CAP * FFN];
__device__ __align__(16) float g_Y[(size_t)NEXP * CAP * DIM];

// ---------------- helpers ----------------
static __device__ __forceinline__ uint32_t smem_u32(const void* p) {
    uint32_t a;
    asm("{ .reg .u64 t; cvta.to.shared.u64 t, %1; cvt.u32.u64 %0, t; }" : "=r"(a) : "l"(p));
    return a;
}
static __device__ __forceinline__ void cpasync16(uint32_t s, const void* g) {
    asm volatile("cp.async.ca.shared.global [%0], [%1], 16;" :: "r"(s), "l"(g));
}
#define CP_COMMIT() asm volatile("cp.async.commit_group;" ::: "memory")
#define CP_WAIT0()  asm volatile("cp.async.wait_group 0;" ::: "memory")

static __device__ __forceinline__ void ldsm4(uint32_t* r, uint32_t addr) {
    asm volatile("ldmatrix.sync.aligned.m8n8.x4.shared.b16 {%0,%1,%2,%3}, [%4];"
        : "=r"(r[0]), "=r"(r[1]), "=r"(r[2]), "=r"(r[3]) : "r"(addr));
}

static __device__ __forceinline__ void mma16816(float* c, const uint32_t* a, const uint32_t* b) {
    asm volatile("mma.sync.aligned.m16n8k16.row.col.f32.bf16.bf16.f32 "
        "{%0,%1,%2,%3}, {%4,%5,%6,%7}, {%8,%9}, {%0,%1,%2,%3};"
        : "+f"(c[0]), "+f"(c[1]), "+f"(c[2]), "+f"(c[3])
        : "r"(a[0]), "r"(a[1]), "r"(a[2]), "r"(a[3]), "r"(b[0]), "r"(b[1]));
}

// fp32 -> bf16 hi + bf16 lo (pairwise packed in b32)
static __device__ __forceinline__ void cvt2(float a0, float a1, uint32_t& hi2, uint32_t& lo2) {
    asm("cvt.rn.bf16x2.f32 %0, %1, %2;" : "=r"(hi2) : "f"(a1), "f"(a0));
    float h0 = __uint_as_float(hi2 << 16);
    float h1 = __uint_as_float(hi2 & 0xffff0000u);
    float l0 = a0 - h0, l1 = a1 - h1;
    asm("cvt.rn.bf16x2.f32 %0, %1, %2;" : "=r"(lo2) : "f"(l1), "f"(l0));
}
static __device__ __forceinline__ void hilo8(float4 a, float4 b, uint4& hi, uint4& lo) {
    cvt2(a.x, a.y, hi.x, lo.x);
    cvt2(a.z, a.w, hi.y, lo.y);
    cvt2(b.x, b.y, hi.z, lo.z);
    cvt2(b.z, b.w, hi.w, lo.w);
}

// ---------------- kernel 0: zero counters ----------------
__global__ void k_zero_counts() {
    if (threadIdx.x < NEXP) g_counts[threadIdx.x] = 0;
}

// ---------------- kernel 1: split x into bf16 hi/lo ----------------
__global__ void __launch_bounds__(256) k_xsplit(const float* __restrict__ x) {
    size_t base = ((size_t)blockIdx.x * 256 + threadIdx.x) * 8;
    float4 a = *(const float4*)(x + base);
    float4 b = *(const float4*)(x + base + 4);
    uint4 hi, lo;
    hilo8(a, b, hi, lo);
    *(uint4*)((uint16_t*)g_xhi + base) = hi;
    *(uint4*)((uint16_t*)g_xlo + base) = lo;
}

// ---------------- kernel 2: gating ----------------
__global__ void __launch_bounds__(128) k_gating(const float* __restrict__ x,
                                                const float* __restrict__ gw) {
    int t = blockIdx.x;
    __shared__ float4 xs4[DIM / 4];
    __shared__ float prob[NEXP];

    int tid = threadIdx.x, lane = tid & 31, warp = tid >> 5;
    const float4* xg = (const float4*)(x + (size_t)t * DIM);
    for (int i = tid; i < DIM / 4; i += 128) xs4[i] = xg[i];
    __syncthreads();

    for (int e = 0; e < 16; e++) {
        int ex = warp * 16 + e;
        const float4* g4 = (const float4*)(gw + (size_t)ex * DIM);
        float s = 0.f;
        for (int j = lane; j < DIM / 4; j += 32) {
            float4 a = g4[j];
            float4 b = xs4[j];
            s += a.x * b.x + a.y * b.y + a.z * b.z + a.w * b.w;
        }
        #pragma unroll
        for (int o = 16; o > 0; o >>= 1) s += __shfl_down_sync(0xffffffffu, s, o);
        if (lane == 0) prob[ex] = s;
    }
    __syncthreads();

    if (warp == 0) {
        float l0 = prob[lane], l1 = prob[lane + 32];
        float m = fmaxf(l0, l1);
        #pragma unroll
        for (int o = 16; o > 0; o >>= 1) m = fmaxf(m, __shfl_xor_sync(0xffffffffu, m, o));
        float p0 = expf(l0 - m), p1 = expf(l1 - m);
        float z = p0 + p1;
        #pragma unroll
        for (int o = 16; o > 0; o >>= 1) z += __shfl_xor_sync(0xffffffffu, z, o);
        float inv = 1.f / z;
        prob[lane] = p0 * inv;
        prob[lane + 32] = p1 * inv;
        __syncwarp();

        for (int k = 0; k < TOPK; k++) {
            float v0 = prob[lane], v1 = prob[lane + 32];
            float bv = v0; int bi = lane;
            if (v1 > v0) { bv = v1; bi = lane + 32; }
            #pragma unroll
            for (int o = 16; o > 0; o >>= 1) {
                float ov = __shfl_down_sync(0xffffffffu, bv, o);
                int   oi = __shfl_down_sync(0xffffffffu, bi, o);
                if (ov > bv || (ov == bv && oi < bi)) { bv = ov; bi = oi; }
            }
            if (lane == 0) {
                int e = bi;
                float s = prob[bi];
                int slot = atomicAdd(&g_counts[e], 1);
                int loc = -1;
                if (slot < CAP) {
                    loc = e * CAP + slot;
                    g_tok[loc] = t;
                    g_score[loc] = s;
                }
                g_loc[t * TOPK + k] = loc;
                prob[bi] = -1.f;
            }
            __syncwarp();
        }
    }
}

// ====================== GEMM smem layout (halves), BK=64 ======================
#define SROW 72
#define STG  55296
#define SMEM_BYTES (2 * STG * 2)   // 221184 B

// FFN1 regions (halves)
#define T1_AH 0
#define T1_AL 9216
#define T1_GH 18432
#define T1_GL 27648
#define T1_UH 36864
#define T1_UL 46080

// FFN2 regions
#define T2_AH 0
#define T2_AL 9216
#define T2_BH 18432
#define T2_BL 36864

// load 16 floats into rq, store as hi/lo bf16 (8+8 halves) at off
#define LD16(g) { rq[0] = ((const float4*)(g))[0]; rq[1] = ((const float4*)(g))[1]; \
                  rq[2] = ((const float4*)(g))[2]; rq[3] = ((const float4*)(g))[3]; }
#define ST16(smh, sml, off) { uint4 _hi, _lo; hilo8(rq[0], rq[1], _hi, _lo); \
                  *(uint4*)&(smh)[off] = _hi; *(uint4*)&(sml)[off] = _lo; \
                  hilo8(rq[2], rq[3], _hi, _lo); \
                  *(uint4*)&(smh)[(off) + 8] = _hi; *(uint4*)&(sml)[(off) + 8] = _lo; }

// ---- FFN1 step: warp tile 64m x 32n (g AND u), 96 MMAs, 16 ldsm.x4 ----
static __device__ __forceinline__ void ffn1_step(uint32_t Sb, int ks, int wm, int wn, int lane,
                                                 float cg[4][4][4], float cu[4][4][4]) {
    const int g = lane >> 3;
    const int jrow = ((g >> 1) << 3) + (lane & 7);
    const int kofB = ks * 16 + ((g & 1) << 3);
    uint32_t bgh[4][2], bgl[4][2], buh[4][2], bul[4][2];
    #pragma unroll
    for (int j2 = 0; j2 < 2; j2++) {
        uint32_t nrow = (uint32_t)(wn * 32 + j2 * 16 + jrow);
        uint32_t bd = Sb + (uint32_t)((T1_GH + nrow * SROW + kofB) * 2);
        ldsm4(&bgh[2 * j2][0], bd);
        ldsm4(&bgl[2 * j2][0], bd + (T1_GL - T1_GH) * 2);
        ldsm4(&buh[2 * j2][0], bd + (T1_UH - T1_GH) * 2);
        ldsm4(&bul[2 * j2][0], bd + (T1_UL - T1_GH) * 2);
    }
    const int kofA = ks * 16 + ((lane >> 4) << 3);
    const int arow_b = wm * 64 + (lane & 15);
    #pragma unroll
    for (int i = 0; i < 4; i++) {
        uint32_t ah[4], al[4];
        uint32_t ad = Sb + (uint32_t)((T1_AH + (arow_b + i * 16) * SROW + kofA) * 2);
        ldsm4(ah, ad);
        ldsm4(al, ad + (T1_AL - T1_AH) * 2);
        #pragma unroll
        for (int j = 0; j < 4; j++) {
            mma16816(cg[i][j], ah, bgh[j]);
            mma16816(cg[i][j], ah, bgl[j]);
            mma16816(cg[i][j], al, bgh[j]);
            mma16816(cu[i][j], ah, buh[j]);
            mma16816(cu[i][j], ah, bul[j]);
            mma16816(cu[i][j], al, buh[j]);
        }
    }
}

// ---------------- kernel 3: grouped GEMM1 (gate+up) + SwiGLU -> Hhi/Hlo ----
// CTA tile: 128 rows x 128 ffn-cols (g and u). BK=64. Warps 2m x 4n (64x32).
__global__ void __launch_bounds__(256, 1) k_ffn1_mma(const float* __restrict__ wg,
                                                     const float* __restrict__ wu) {
    extern __shared__ __align__(16) uint16_t sm[];
    const int e = blockIdx.z;
    const int cnt = min(g_counts[e], CAP);
    const int m0 = blockIdx.y * 128;
    if (m0 >= cnt) return;
    const int n0 = blockIdx.x * 128;
    const int tid = threadIdx.x;
    const uint32_t sbase = smem_u32(sm);

    // A loader: row = tid>>1, 32-half seg = (tid&1)*32
    const int arow = tid >> 1, ak = (tid & 1) * 32;
    const int tr = m0 + arow;
    const int tok = (tr < cnt) ? g_tok[e * CAP + tr] : 0;
    const uint16_t* gah = (const uint16_t*)g_xhi + (size_t)tok * DIM + ak;
    const uint16_t* gal = (const uint16_t*)g_xlo + (size_t)tok * DIM + ak;
    const uint32_t sAoff = (uint32_t)(arow * SROW + ak) * 2;

    // B loader: col-row = tid>>1 (0..127), 32-float half = (tid&1)*32
    const int brow = tid >> 1, bhalf = (tid & 1) * 32;
    const float* gbg = wg + (size_t)e * FFN * DIM + (size_t)(n0 + brow) * DIM + bhalf;
    const float* gbu = wu + (size_t)e * FFN * DIM + (size_t)(n0 + brow) * DIM + bhalf;
    const uint32_t sB = (uint32_t)(brow * SROW + bhalf);

    const int wid = tid >> 5, lane = tid & 31;
    const int wm = wid >> 2, wn = wid & 3;
    const int fg = lane >> 2, ft = lane & 3;

    float cg[4][4][4] = {};
    float cu[4][4][4] = {};
    float4 rq[4];

    // prologue: A0 via cp.async; B0 convert+store into stage 0
    {
        uint32_t d = sbase + sAoff;
        cpasync16(d, gah); cpasync16(d + 16, gah + 8);
        cpasync16(d + 32, gah + 16); cpasync16(d + 48, gah + 24);
        uint32_t dl = d + T1_AL * 2;
        cpasync16(dl, gal); cpasync16(dl + 16, gal + 8);
        cpasync16(dl + 32, gal + 16); cpasync16(dl + 48, gal + 24);
        CP_COMMIT();
        LD16(gbg);      ST16(sm + T1_GH, sm + T1_GL, sB);
        LD16(gbg + 16); ST16(sm + T1_GH, sm + T1_GL, sB + 16);
        LD16(gbu);      ST16(sm + T1_UH, sm + T1_UL, sB);
        LD16(gbu + 16); ST16(sm + T1_UH, sm + T1_UL, sB + 16);
    }

    const int C = DIM / 64;
    for (int c = 0; c < C; c++) {
        const int st = c & 1;
        const uint32_t Sb = sbase + (uint32_t)st * (STG * 2);
        uint16_t* Sn = sm + (st ^ 1) * STG;
        CP_WAIT0();
        __syncthreads();
        const bool more = (c + 1 < C);
        const int kkn = (c + 1) * 64;
        if (more) {
            uint32_t d = sbase + (uint32_t)(st ^ 1) * (STG * 2) + sAoff;
            cpasync16(d, gah + kkn); cpasync16(d + 16, gah + kkn + 8);
            cpasync16(d + 32, gah + kkn + 16); cpasync16(d + 48, gah + kkn + 24);
            uint32_t dl = d + T1_AL * 2;
            cpasync16(dl, gal + kkn); cpasync16(dl + 16, gal + kkn + 8);
            cpasync16(dl + 32, gal + kkn + 16); cpasync16(dl + 48, gal + kkn + 24);
            CP_COMMIT();
            LD16(gbg + kkn);
        }
        ffn1_step(Sb, 0, wm, wn, lane, cg, cu);
        if (more) { ST16(Sn + T1_GH, Sn + T1_GL, sB); LD16(gbg + kkn + 16); }
        ffn1_step(Sb, 1, wm, wn, lane, cg, cu);
        if (more) { ST16(Sn + T1_GH, Sn + T1_GL, sB + 16); LD16(gbu + kkn); }
        ffn1_step(Sb, 2, wm, wn, lane, cg, cu);
        if (more) { ST16(Sn + T1_UH, Sn + T1_UL, sB); LD16(gbu + kkn + 16); }
        ffn1_step(Sb, 3, wm, wn, lane, cg, cu);
        if (more) { ST16(Sn + T1_UH, Sn + T1_UL, sB + 16); }
    }

    // epilogue: h = silu(g)*u -> bf16 hi/lo
    uint16_t* hh = (uint16_t*)g_Hhi;
    uint16_t* hl = (uint16_t*)g_Hlo;
    const size_t ebase = (size_t)e * CAP;
    #pragma unroll
    for (int i = 0; i < 4; i++)
        #pragma unroll
        for (int j = 0; j < 4; j++) {
            const int r0 = m0 + wm * 64 + i * 16 + fg;
            const int col = n0 + wn * 32 + j * 8 + ft * 2;
            #pragma unroll
            for (int h = 0; h < 2; h++) {
                const int r = r0 + h * 8;
                float gv0 = cg[i][j][2 * h], gv1 = cg[i][j][2 * h + 1];
                float uv0 = cu[i][j][2 * h], uv1 = cu[i][j][2 * h + 1];
                float h0 = gv0 / (1.f + __expf(-gv0)) * uv0;
                float h1 = gv1 / (1.f + __expf(-gv1)) * uv1;
                uint32_t hi, lo;
                cvt2(h0, h1, hi, lo);
                *(uint32_t*)&hh[(ebase + r) * FFN + col] = hi;
                *(uint32_t*)&hl[(ebase + r) * FFN + col] = lo;
            }
        }
}

// ---- FFN2 step: warp tile 64m x 64n, 96 MMAs, 16 ldsm.x4 ----
static __device__ __forceinline__ void ffn2_step(uint32_t Sb, int ks, int wm, int wn, int lane,
                                                 float cd[4][8][4]) {
    const int g = lane >> 3;
    const int jrow = ((g >> 1) << 3) + (lane & 7);
    const int kofB = ks * 16 + ((g & 1) << 3);
    uint32_t bh[8][2], bl[8][2];
    #pragma unroll
    for (int j2 = 0; j2 < 4; j2++) {
        uint32_t nrow = (uint32_t)(wn * 64 + j2 * 16 + jrow);
        uint32_t bd = Sb + (uint32_t)((T2_BH + nrow * SROW + kofB) * 2);
        ldsm4(&bh[2 * j2][0], bd);
        ldsm4(&bl[2 * j2][0], bd + (T2_BL - T2_BH) * 2);
    }
    const int kofA = ks * 16 + ((lane >> 4) << 3);
    const int arow_b = wm * 64 + (lane & 15);
    #pragma unroll
    for (int i = 0; i < 4; i++) {
        uint32_t ah[4], al[4];
        uint32_t ad = Sb + (uint32_t)((T2_AH + (arow_b + i * 16) * SROW + kofA) * 2);
        ldsm4(ah, ad);
        ldsm4(al, ad + (T2_AL - T2_AH) * 2);
        #pragma unroll
        for (int j = 0; j < 8; j++) {
            mma16816(cd[i][j], ah, bh[j]);
            mma16816(cd[i][j], ah, bl[j]);
            mma16816(cd[i][j], al, bh[j]);
        }
    }
}

// ---------------- kernel 4: grouped GEMM2 (H @ w_down^T)*score -> Y --------
// CTA tile: 128 rows x 256 D-cols. BK=64. Warps 2m x 4n (64x64).
__global__ void __launch_bounds__(256, 1) k_ffn2_mma(const float* __restrict__ wd) {
    extern __shared__ __align__(16) uint16_t sm[];
    const int e = blockIdx.z;
    const int cnt = min(g_counts[e], CAP);
    const int m0 = blockIdx.y * 128;
    if (m0 >= cnt) return;
    const int n0 = blockIdx.x * 256;
    const int tid = threadIdx.x;
    const uint32_t sbase = smem_u32(sm);

    const int arow = tid >> 1, ak = (tid & 1) * 32;
    const uint16_t* gah = (const uint16_t*)g_Hhi + ((size_t)e * CAP + m0 + arow) * FFN + ak;
    const uint16_t* gal = (const uint16_t*)g_Hlo + ((size_t)e * CAP + m0 + arow) * FFN + ak;
    const uint32_t sAoff = (uint32_t)(arow * SROW + ak) * 2;

    // B loader: one w_down row (D-col) per thread, 64 floats in 4 quarters
    const float* gb = wd + (size_t)e * DIM * FFN + (size_t)(n0 + tid) * FFN;
    const uint32_t sB = (uint32_t)(tid * SROW);

    const int wid = tid >> 5, lane = tid & 31;
    const int wm = wid >> 2, wn = wid & 3;
    const int fg = lane >> 2, ft = lane & 3;

    float cd[4][8][4] = {};
    float4 rq[4];

    {
        uint32_t d = sbase + sAoff;
        cpasync16(d, gah); cpasync16(d + 16, gah + 8);
        cpasync16(d + 32, gah + 16); cpasync16(d + 48, gah + 24);
        uint32_t dl = d + T2_AL * 2;
        cpasync16(dl, gal); cpasync16(dl + 16, gal + 8);
        cpasync16(dl + 32, gal + 16); cpasync16(dl + 48, gal + 24);
        CP_COMMIT();
        LD16(gb);      ST16(sm + T2_BH, sm + T2_BL, sB);
        LD16(gb + 16); ST16(sm + T2_BH, sm + T2_BL, sB + 16);
        LD16(gb + 32); ST16(sm + T2_BH, sm + T2_BL, sB + 32);
        LD16(gb + 48); ST16(sm + T2_BH, sm + T2_BL, sB + 48);
    }

    const int C = FFN / 64;
    for (int c = 0; c < C; c++) {
        const int st = c & 1;
        const uint32_t Sb = sbase + (uint32_t)st * (STG * 2);
        uint16_t* Sn = sm + (st ^ 1) * STG;
        CP_WAIT0();
        __syncthreads();
        const bool more = (c + 1 < C);
        const int kkn = (c + 1) * 64;
        if (more) {
            uint32_t d = sbase + (uint32_t)(st ^ 1) * (STG * 2) + sAoff;
            cpasync16(d, gah + kkn); cpasync16(d + 16, gah + kkn + 8);
            cpasync16(d + 32, gah + kkn + 16); cpasync16(d + 48, gah + kkn + 24);
            uint32_t dl = d + T2_AL * 2;
            cpasync16(dl, gal + kkn); cpasync16(dl + 16, gal + kkn + 8);
            cpasync16(dl + 32, gal + kkn + 16); cpasync16(dl + 48, gal + kkn + 24);
            CP_COMMIT();
            LD16(gb + kkn);
        }
        ffn2_step(Sb, 0, wm, wn, lane, cd);
        if (more) { ST16(Sn + T2_BH, Sn + T2_BL, sB); LD16(gb + kkn + 16); }
        ffn2_step(Sb, 1, wm, wn, lane, cd);
        if (more) { ST16(Sn + T2_BH, Sn + T2_BL, sB + 16); LD16(gb + kkn + 32); }
        ffn2_step(Sb, 2, wm, wn, lane, cd);
        if (more) { ST16(Sn + T2_BH, Sn + T2_BL, sB + 32); LD16(gb + kkn + 48); }
        ffn2_step(Sb, 3, wm, wn, lane, cd);
        if (more) { ST16(Sn + T2_BH, Sn + T2_BL, sB + 48); }
    }

    // epilogue: y * score -> g_Y
    const size_t ebase = (size_t)e * CAP;
    #pragma unroll
    for (int i = 0; i < 4; i++) {
        const int r0 = m0 + wm * 64 + i * 16 + fg;
        #pragma unroll
        for (int h = 0; h < 2; h++) {
            const int r = r0 + h * 8;
            const float s = g_score[ebase + r];
            float* yrow = g_Y + (ebase + r) * DIM;
            #pragma unroll
            for (int j = 0; j < 8; j++) {
                const int col = n0 + wn * 64 + j * 8 + ft * 2;
                float2 o;
                o.x = cd[i][j][2 * h] * s;
                o.y = cd[i][j][2 * h + 1] * s;
                *(float2*)&yrow[col] = o;
            }
        }
    }
}

// ---------------- kernel 5: combine ----------------
__global__ void __launch_bounds__(256) k_combine(float* __restrict__ out) {
    int t = blockIdx.x;
    int tid = threadIdx.x;
    float4 a0 = make_float4(0.f, 0.f, 0.f, 0.f);
    float4 a1 = make_float4(0.f, 0.f, 0.f, 0.f);
    #pragma unroll
    for (int k = 0; k < TOPK; k++) {
        int loc = g_loc[t * TOPK + k];
        if (loc < 0) continue;
        const float4* y = (const float4*)(g_Y + (size_t)loc * DIM);
        float4 v0 = y[tid * 2], v1 = y[tid * 2 + 1];
        a0.x += v0.x; a0.y += v0.y; a0.z += v0.z; a0.w += v0.w;
        a1.x += v1.x; a1.y += v1.y; a1.z += v1.z; a1.w += v1.w;
    }
    float4* o = (float4*)(out + (size_t)t * DIM);
    o[tid * 2] = a0;
    o[tid * 2 + 1] = a1;
}

// ---------------- launch ----------------
extern "C" void kernel_launch(void* const* d_in, const int* in_sizes, int n_in,
                              void* d_out, int out_size) {
    const float* x  = (const float*)d_in[0];   // hidden_states [1,2048,2048]
    const float* gw = (const float*)d_in[1];   // gate_w  [64,2048]
    const float* wg = (const float*)d_in[2];   // w_gate  [64,768,2048]
    const float* wu = (const float*)d_in[3];   // w_up    [64,768,2048]
    const float* wd = (const float*)d_in[4];   // w_down  [64,2048,768]
    float* out = (float*)d_out;

    cudaFuncSetAttribute(k_ffn1_mma, cudaFuncAttributeMaxDynamicSharedMemorySize, SMEM_BYTES);
    cudaFuncSetAttribute(k_ffn2_mma, cudaFuncAttributeMaxDynamicSharedMemorySize, SMEM_BYTES);

    k_zero_counts<<<1, 64>>>();
    k_xsplit<<<(NTOK * DIM) / (256 * 8), 256>>>(x);
    k_gating<<<NTOK, 128>>>(x, gw);
    k_ffn1_mma<<<dim3(FFN / 128, CAP / 128, NEXP), 256, SMEM_BYTES>>>(wg, wu);
    k_ffn2_mma<<<dim3(DIM / 256, CAP / 128, NEXP), 256, SMEM_BYTES>>>(wd);
    k_combine<<<NTOK, 256>>>(out);
}

// round 14
// speedup vs baseline: 1.0327x; 1.0327x over previous
#include <cuda_runtime.h>
#include <cuda_bf16.h>
#include <stdint.h>
#include <math.h>

#define NTOK 2048
#define DIM  2048
#define NEXP 64
#define TOPK 8
#define FFN  768
#define CAP  512

// ---------------- device scratch ----------------
__device__ int   g_counts[NEXP];
__device__ int   g_tok[NEXP * CAP];
__device__ float g_score[NEXP * CAP];
__device__ int   g_loc[NTOK * TOPK];
__device__ __align__(16) __nv_bfloat16 g_xhi[(size_t)NTOK * DIM];
__device__ __align__(16) __nv_bfloat16 g_xlo[(size_t)NTOK * DIM];
__device__ __align__(16) __nv_bfloat16 g_Hhi[(size_t)NEXP * CAP * FFN];
__device__ __align__(16) __nv_bfloat16 g_Hlo[(size_t)NEXP * CAP * FFN];
__device__ __align__(16) float g_Y[(size_t)NEXP * CAP * DIM];

// ---------------- helpers ----------------
static __device__ __forceinline__ uint32_t smem_u32(const void* p) {
    uint32_t a;
    asm("{ .reg .u64 t; cvta.to.shared.u64 t, %1; cvt.u32.u64 %0, t; }" : "=r"(a) : "l"(p));
    return a;
}
static __device__ __forceinline__ void cpasync16(uint32_t s, const void* g) {
    asm volatile("cp.async.ca.shared.global [%0], [%1], 16;" :: "r"(s), "l"(g));
}
#define CP_COMMIT() asm volatile("cp.async.commit_group;" ::: "memory")
#define CP_WAIT0()  asm volatile("cp.async.wait_group 0;" ::: "memory")

static __device__ __forceinline__ void ldsm4(uint32_t* r, uint32_t addr) {
    asm volatile("ldmatrix.sync.aligned.m8n8.x4.shared.b16 {%0,%1,%2,%3}, [%4];"
        : "=r"(r[0]), "=r"(r[1]), "=r"(r[2]), "=r"(r[3]) : "r"(addr));
}

static __device__ __forceinline__ void mma16816(float* c, const uint32_t* a, const uint32_t* b) {
    asm volatile("mma.sync.aligned.m16n8k16.row.col.f32.bf16.bf16.f32 "
        "{%0,%1,%2,%3}, {%4,%5,%6,%7}, {%8,%9}, {%0,%1,%2,%3};"
        : "+f"(c[0]), "+f"(c[1]), "+f"(c[2]), "+f"(c[3])
        : "r"(a[0]), "r"(a[1]), "r"(a[2]), "r"(a[3]), "r"(b[0]), "r"(b[1]));
}

// fp32 -> bf16 hi + bf16 lo (pairwise packed in b32)
static __device__ __forceinline__ void cvt2(float a0, float a1, uint32_t& hi2, uint32_t& lo2) {
    asm("cvt.rn.bf16x2.f32 %0, %1, %2;" : "=r"(hi2) : "f"(a1), "f"(a0));
    float h0 = __uint_as_float(hi2 << 16);
    float h1 = __uint_as_float(hi2 & 0xffff0000u);
    float l0 = a0 - h0, l1 = a1 - h1;
    asm("cvt.rn.bf16x2.f32 %0, %1, %2;" : "=r"(lo2) : "f"(l1), "f"(l0));
}
static __device__ __forceinline__ void hilo8(float4 a, float4 b, uint4& hi, uint4& lo) {
    cvt2(a.x, a.y, hi.x, lo.x);
    cvt2(a.z, a.w, hi.y, lo.y);
    cvt2(b.x, b.y, hi.z, lo.z);
    cvt2(b.z, b.w, hi.w, lo.w);
}

// ---------------- kernel 0: zero counters ----------------
__global__ void k_zero_counts() {
    if (threadIdx.x < NEXP) g_counts[threadIdx.x] = 0;
}

// ---------------- kernel 1: split x into bf16 hi/lo ----------------
__global__ void __launch_bounds__(256) k_xsplit(const float* __restrict__ x) {
    size_t base = ((size_t)blockIdx.x * 256 + threadIdx.x) * 8;
    float4 a = *(const float4*)(x + base);
    float4 b = *(const float4*)(x + base + 4);
    uint4 hi, lo;
    hilo8(a, b, hi, lo);
    *(uint4*)((uint16_t*)g_xhi + base) = hi;
    *(uint4*)((uint16_t*)g_xlo + base) = lo;
}

// ---------------- kernel 2: gating ----------------
__global__ void __launch_bounds__(128) k_gating(const float* __restrict__ x,
                                                const float* __restrict__ gw) {
    int t = blockIdx.x;
    __shared__ float4 xs4[DIM / 4];
    __shared__ float prob[NEXP];

    int tid = threadIdx.x, lane = tid & 31, warp = tid >> 5;
    const float4* xg = (const float4*)(x + (size_t)t * DIM);
    for (int i = tid; i < DIM / 4; i += 128) xs4[i] = xg[i];
    __syncthreads();

    for (int e = 0; e < 16; e++) {
        int ex = warp * 16 + e;
        const float4* g4 = (const float4*)(gw + (size_t)ex * DIM);
        float s = 0.f;
        for (int j = lane; j < DIM / 4; j += 32) {
            float4 a = g4[j];
            float4 b = xs4[j];
            s += a.x * b.x + a.y * b.y + a.z * b.z + a.w * b.w;
        }
        #pragma unroll
        for (int o = 16; o > 0; o >>= 1) s += __shfl_down_sync(0xffffffffu, s, o);
        if (lane == 0) prob[ex] = s;
    }
    __syncthreads();

    if (warp == 0) {
        float l0 = prob[lane], l1 = prob[lane + 32];
        float m = fmaxf(l0, l1);
        #pragma unroll
        for (int o = 16; o > 0; o >>= 1) m = fmaxf(m, __shfl_xor_sync(0xffffffffu, m, o));
        float p0 = expf(l0 - m), p1 = expf(l1 - m);
        float z = p0 + p1;
        #pragma unroll
        for (int o = 16; o > 0; o >>= 1) z += __shfl_xor_sync(0xffffffffu, z, o);
        float inv = 1.f / z;
        prob[lane] = p0 * inv;
        prob[lane + 32] = p1 * inv;
        __syncwarp();

        for (int k = 0; k < TOPK; k++) {
            float v0 = prob[lane], v1 = prob[lane + 32];
            float bv = v0; int bi = lane;
            if (v1 > v0) { bv = v1; bi = lane + 32; }
            #pragma unroll
            for (int o = 16; o > 0; o >>= 1) {
                float ov = __shfl_down_sync(0xffffffffu, bv, o);
                int   oi = __shfl_down_sync(0xffffffffu, bi, o);
                if (ov > bv || (ov == bv && oi < bi)) { bv = ov; bi = oi; }
            }
            if (lane == 0) {
                int e = bi;
                float s = prob[bi];
                int slot = atomicAdd(&g_counts[e], 1);
                int loc = -1;
                if (slot < CAP) {
                    loc = e * CAP + slot;
                    g_tok[loc] = t;
                    g_score[loc] = s;
                }
                g_loc[t * TOPK + k] = loc;
                prob[bi] = -1.f;
            }
            __syncwarp();
        }
    }
}

// ====================== GEMM smem layout (halves), BK=32 ======================
#define SROW 40
#define STAGE_H 30720
#define SMEM_BYTES (2 * STAGE_H * 2)   // 122880 B

// FFN1 regions (halves): A 128 rows, Bg 128 cols, Bu 128 cols
#define S1_AH 0
#define S1_AL 5120
#define S1_GH 10240
#define S1_GL 15360
#define S1_UH 20480
#define S1_UL 25600

// FFN2 regions: A 128 rows, B 256 cols
#define S2_AH 0
#define S2_AL 5120
#define S2_BH 10240
#define S2_BL 20480

// load 16 floats into rq; store as hi/lo bf16 (16+16 halves) at off
#define LD16(g) { rq[0] = ((const float4*)(g))[0]; rq[1] = ((const float4*)(g))[1]; \
                  rq[2] = ((const float4*)(g))[2]; rq[3] = ((const float4*)(g))[3]; }
#define ST16(smh, sml, off) { uint4 _hi, _lo; hilo8(rq[0], rq[1], _hi, _lo); \
                  *(uint4*)&(smh)[off] = _hi; *(uint4*)&(sml)[off] = _lo; \
                  hilo8(rq[2], rq[3], _hi, _lo); \
                  *(uint4*)&(smh)[(off) + 8] = _hi; *(uint4*)&(sml)[(off) + 8] = _lo; }

// ---- FFN1 g-phase: 8 B-ldsm-regs live, 48 MMAs ----
static __device__ __forceinline__ void ffn1_step_g(uint32_t Sb, int ks, int wm, int wn, int lane,
                                                   float cg[4][4][4]) {
    const int g = lane >> 3;
    const int jrow = ((g >> 1) << 3) + (lane & 7);
    const int kofB = ks * 16 + ((g & 1) << 3);
    uint32_t bgh[4][2], bgl[4][2];
    #pragma unroll
    for (int j2 = 0; j2 < 2; j2++) {
        uint32_t nrow = (uint32_t)(wn * 32 + j2 * 16 + jrow);
        uint32_t bd = Sb + (uint32_t)((S1_GH + nrow * SROW + kofB) * 2);
        ldsm4(&bgh[2 * j2][0], bd);
        ldsm4(&bgl[2 * j2][0], bd + (S1_GL - S1_GH) * 2);
    }
    const int kofA = ks * 16 + ((lane >> 4) << 3);
    const int arow_b = wm * 64 + (lane & 15);
    #pragma unroll
    for (int i = 0; i < 4; i++) {
        uint32_t ah[4], al[4];
        uint32_t ad = Sb + (uint32_t)((S1_AH + (arow_b + i * 16) * SROW + kofA) * 2);
        ldsm4(ah, ad);
        ldsm4(al, ad + (S1_AL - S1_AH) * 2);
        #pragma unroll
        for (int j = 0; j < 4; j++) {
            mma16816(cg[i][j], ah, bgh[j]);
            mma16816(cg[i][j], ah, bgl[j]);
            mma16816(cg[i][j], al, bgh[j]);
        }
    }
}

// ---- FFN1 u-phase ----
static __device__ __forceinline__ void ffn1_step_u(uint32_t Sb, int ks, int wm, int wn, int lane,
                                                   float cu[4][4][4]) {
    const int g = lane >> 3;
    const int jrow = ((g >> 1) << 3) + (lane & 7);
    const int kofB = ks * 16 + ((g & 1) << 3);
    uint32_t buh[4][2], bul[4][2];
    #pragma unroll
    for (int j2 = 0; j2 < 2; j2++) {
        uint32_t nrow = (uint32_t)(wn * 32 + j2 * 16 + jrow);
        uint32_t bd = Sb + (uint32_t)((S1_UH + nrow * SROW + kofB) * 2);
        ldsm4(&buh[2 * j2][0], bd);
        ldsm4(&bul[2 * j2][0], bd + (S1_UL - S1_UH) * 2);
    }
    const int kofA = ks * 16 + ((lane >> 4) << 3);
    const int arow_b = wm * 64 + (lane & 15);
    #pragma unroll
    for (int i = 0; i < 4; i++) {
        uint32_t ah[4], al[4];
        uint32_t ad = Sb + (uint32_t)((S1_AH + (arow_b + i * 16) * SROW + kofA) * 2);
        ldsm4(ah, ad);
        ldsm4(al, ad + (S1_AL - S1_AH) * 2);
        #pragma unroll
        for (int j = 0; j < 4; j++) {
            mma16816(cu[i][j], ah, buh[j]);
            mma16816(cu[i][j], ah, bul[j]);
            mma16816(cu[i][j], al, buh[j]);
        }
    }
}

// ---------------- kernel 3: grouped GEMM1 (gate+up) + SwiGLU -> Hhi/Hlo ----
// CTA tile: 128 rows x 128 ffn-cols (g and u). BK=32. Warps 2m x 4n (64x32).
__global__ void __launch_bounds__(256, 1) k_ffn1_mma(const float* __restrict__ wg,
                                                     const float* __restrict__ wu) {
    extern __shared__ __align__(16) uint16_t sm[];
    const int e = blockIdx.z;
    const int cnt = min(g_counts[e], CAP);
    const int m0 = blockIdx.y * 128;
    if (m0 >= cnt) return;
    const int n0 = blockIdx.x * 128;
    const int tid = threadIdx.x;
    const uint32_t sbase = smem_u32(sm);

    // A loader: row = tid>>1, 16-half seg = tid&1
    const int arow = tid >> 1, ak = (tid & 1) * 16;
    const int tr = m0 + arow;
    const int tok = (tr < cnt) ? g_tok[e * CAP + tr] : 0;
    const uint16_t* gah = (const uint16_t*)g_xhi + (size_t)tok * DIM + ak;
    const uint16_t* gal = (const uint16_t*)g_xlo + (size_t)tok * DIM + ak;
    const uint32_t sAoff = (uint32_t)(arow * SROW + ak) * 2;

    // B loader: col-row = tid>>1 (0..127), 16-float seg = (tid&1)*16
    const int brow = tid >> 1, bk = (tid & 1) * 16;
    const float* gbg = wg + (size_t)e * FFN * DIM + (size_t)(n0 + brow) * DIM + bk;
    const float* gbu = wu + (size_t)e * FFN * DIM + (size_t)(n0 + brow) * DIM + bk;
    const uint32_t sB = (uint32_t)(brow * SROW + bk);

    const int wid = tid >> 5, lane = tid & 31;
    const int wm = wid >> 2, wn = wid & 3;
    const int fg = lane >> 2, ft = lane & 3;

    float cg[4][4][4] = {};
    float cu[4][4][4] = {};
    float4 rq[4];

    // prologue: A0 via cp.async, B0 convert+store into stage 0
    {
        uint32_t d = sbase + sAoff;
        cpasync16(d, gah); cpasync16(d + 16, gah + 8);
        cpasync16(d + S1_AL * 2, gal); cpasync16(d + S1_AL * 2 + 16, gal + 8);
        CP_COMMIT();
        LD16(gbg); ST16(sm + S1_GH, sm + S1_GL, sB);
        LD16(gbu); ST16(sm + S1_UH, sm + S1_UL, sB);
    }

    const int C = DIM / 32;
    for (int c = 0; c < C; c++) {
        const int st = c & 1;
        const uint32_t Sb = sbase + (uint32_t)st * (STAGE_H * 2);
        uint16_t* Sn = sm + (st ^ 1) * STAGE_H;
        CP_WAIT0();
        __syncthreads();
        const bool more = (c + 1 < C);
        const int kkn = (c + 1) * 32;
        if (more) {
            uint32_t d = sbase + (uint32_t)(st ^ 1) * (STAGE_H * 2) + sAoff;
            cpasync16(d, gah + kkn); cpasync16(d + 16, gah + kkn + 8);
            cpasync16(d + S1_AL * 2, gal + kkn); cpasync16(d + S1_AL * 2 + 16, gal + kkn + 8);
            CP_COMMIT();
            LD16(gbg + kkn);
        }
        ffn1_step_g(Sb, 0, wm, wn, lane, cg);
        if (more) { ST16(Sn + S1_GH, Sn + S1_GL, sB); LD16(gbu + kkn); }
        ffn1_step_u(Sb, 0, wm, wn, lane, cu);
        ffn1_step_g(Sb, 1, wm, wn, lane, cg);
        if (more) { ST16(Sn + S1_UH, Sn + S1_UL, sB); }
        ffn1_step_u(Sb, 1, wm, wn, lane, cu);
    }

    // epilogue: h = silu(g)*u -> bf16 hi/lo
    uint16_t* hh = (uint16_t*)g_Hhi;
    uint16_t* hl = (uint16_t*)g_Hlo;
    const size_t ebase = (size_t)e * CAP;
    #pragma unroll
    for (int i = 0; i < 4; i++)
        #pragma unroll
        for (int j = 0; j < 4; j++) {
            const int r0 = m0 + wm * 64 + i * 16 + fg;
            const int col = n0 + wn * 32 + j * 8 + ft * 2;
            #pragma unroll
            for (int h = 0; h < 2; h++) {
                const int r = r0 + h * 8;
                float gv0 = cg[i][j][2 * h], gv1 = cg[i][j][2 * h + 1];
                float uv0 = cu[i][j][2 * h], uv1 = cu[i][j][2 * h + 1];
                float h0 = gv0 / (1.f + __expf(-gv0)) * uv0;
                float h1 = gv1 / (1.f + __expf(-gv1)) * uv1;
                uint32_t hi, lo;
                cvt2(h0, h1, hi, lo);
                *(uint32_t*)&hh[(ebase + r) * FFN + col] = hi;
                *(uint32_t*)&hl[(ebase + r) * FFN + col] = lo;
            }
        }
}

// ---- FFN2 half-step: j-half (0: cols 0..31, 1: cols 32..63 of warp tile), 48 MMAs ----
static __device__ __forceinline__ void ffn2_step_h(uint32_t Sb, int ks, int jh, int wm, int wn,
                                                   int lane, float cd[4][8][4]) {
    const int g = lane >> 3;
    const int jrow = ((g >> 1) << 3) + (lane & 7);
    const int kofB = ks * 16 + ((g & 1) << 3);
    uint32_t bh[4][2], bl[4][2];
    #pragma unroll
    for (int j2 = 0; j2 < 2; j2++) {
        uint32_t nrow = (uint32_t)(wn * 64 + jh * 32 + j2 * 16 + jrow);
        uint32_t bd = Sb + (uint32_t)((S2_BH + nrow * SROW + kofB) * 2);
        ldsm4(&bh[2 * j2][0], bd);
        ldsm4(&bl[2 * j2][0], bd + (S2_BL - S2_BH) * 2);
    }
    const int kofA = ks * 16 + ((lane >> 4) << 3);
    const int arow_b = wm * 64 + (lane & 15);
    #pragma unroll
    for (int i = 0; i < 4; i++) {
        uint32_t ah[4], al[4];
        uint32_t ad = Sb + (uint32_t)((S2_AH + (arow_b + i * 16) * SROW + kofA) * 2);
        ldsm4(ah, ad);
        ldsm4(al, ad + (S2_AL - S2_AH) * 2);
        #pragma unroll
        for (int j = 0; j < 4; j++) {
            mma16816(cd[i][jh * 4 + j], ah, bh[j]);
            mma16816(cd[i][jh * 4 + j], ah, bl[j]);
            mma16816(cd[i][jh * 4 + j], al, bh[j]);
        }
    }
}

// ---------------- kernel 4: grouped GEMM2 (H @ w_down^T)*score -> Y --------
// CTA tile: 128 rows x 256 D-cols. BK=32. Warps 2m x 4n (64x64).
__global__ void __launch_bounds__(256, 1) k_ffn2_mma(const float* __restrict__ wd) {
    extern __shared__ __align__(16) uint16_t sm[];
    const int e = blockIdx.z;
    const int cnt = min(g_counts[e], CAP);
    const int m0 = blockIdx.y * 128;
    if (m0 >= cnt) return;
    const int n0 = blockIdx.x * 256;
    const int tid = threadIdx.x;
    const uint32_t sbase = smem_u32(sm);

    const int arow = tid >> 1, ak = (tid & 1) * 16;
    const uint16_t* gah = (const uint16_t*)g_Hhi + ((size_t)e * CAP + m0 + arow) * FFN + ak;
    const uint16_t* gal = (const uint16_t*)g_Hlo + ((size_t)e * CAP + m0 + arow) * FFN + ak;
    const uint32_t sAoff = (uint32_t)(arow * SROW + ak) * 2;

    // B loader: one w_down row (D-col) per thread, 32 floats in 2 halves
    const float* gb = wd + (size_t)e * DIM * FFN + (size_t)(n0 + tid) * FFN;
    const uint32_t sB = (uint32_t)(tid * SROW);

    const int wid = tid >> 5, lane = tid & 31;
    const int wm = wid >> 2, wn = wid & 3;
    const int fg = lane >> 2, ft = lane & 3;

    float cd[4][8][4] = {};
    float4 rq[4];

    {
        uint32_t d = sbase + sAoff;
        cpasync16(d, gah); cpasync16(d + 16, gah + 8);
        cpasync16(d + S2_AL * 2, gal); cpasync16(d + S2_AL * 2 + 16, gal + 8);
        CP_COMMIT();
        LD16(gb);      ST16(sm + S2_BH, sm + S2_BL, sB);
        LD16(gb + 16); ST16(sm + S2_BH, sm + S2_BL, sB + 16);
    }

    const int C = FFN / 32;
    for (int c = 0; c < C; c++) {
        const int st = c & 1;
        const uint32_t Sb = sbase + (uint32_t)st * (STAGE_H * 2);
        uint16_t* Sn = sm + (st ^ 1) * STAGE_H;
        CP_WAIT0();
        __syncthreads();
        const bool more = (c + 1 < C);
        const int kkn = (c + 1) * 32;
        if (more) {
            uint32_t d = sbase + (uint32_t)(st ^ 1) * (STAGE_H * 2) + sAoff;
            cpasync16(d, gah + kkn); cpasync16(d + 16, gah + kkn + 8);
            cpasync16(d + S2_AL * 2, gal + kkn); cpasync16(d + S2_AL * 2 + 16, gal + kkn + 8);
            CP_COMMIT();
            LD16(gb + kkn);
        }
        ffn2_step_h(Sb, 0, 0, wm, wn, lane, cd);
        if (more) { ST16(Sn + S2_BH, Sn + S2_BL, sB); LD16(gb + kkn + 16); }
        ffn2_step_h(Sb, 0, 1, wm, wn, lane, cd);
        ffn2_step_h(Sb, 1, 0, wm, wn, lane, cd);
        if (more) { ST16(Sn + S2_BH, Sn + S2_BL, sB + 16); }
        ffn2_step_h(Sb, 1, 1, wm, wn, lane, cd);
    }

    // epilogue: y * score -> g_Y
    const size_t ebase = (size_t)e * CAP;
    #pragma unroll
    for (int i = 0; i < 4; i++) {
        const int r0 = m0 + wm * 64 + i * 16 + fg;
        #pragma unroll
        for (int h = 0; h < 2; h++) {
            const int r = r0 + h * 8;
            const float s = g_score[ebase + r];
            float* yrow = g_Y + (ebase + r) * DIM;
            #pragma unroll
            for (int j = 0; j < 8; j++) {
                const int col = n0 + wn * 64 + j * 8 + ft * 2;
                float2 o;
                o.x = cd[i][j][2 * h] * s;
                o.y = cd[i][j][2 * h + 1] * s;
                *(float2*)&yrow[col] = o;
            }
        }
    }
}

// ---------------- kernel 5: combine ----------------
__global__ void __launch_bounds__(256) k_combine(float* __restrict__ out) {
    int t = blockIdx.x;
    int tid = threadIdx.x;
    float4 a0 = make_float4(0.f, 0.f, 0.f, 0.f);
    float4 a1 = make_float4(0.f, 0.f, 0.f, 0.f);
    #pragma unroll
    for (int k = 0; k < TOPK; k++) {
        int loc = g_loc[t * TOPK + k];
        if (loc < 0) continue;
        const float4* y = (const float4*)(g_Y + (size_t)loc * DIM);
        float4 v0 = y[tid * 2], v1 = y[tid * 2 + 1];
        a0.x += v0.x; a0.y += v0.y; a0.z += v0.z; a0.w += v0.w;
        a1.x += v1.x; a1.y += v1.y; a1.z += v1.z; a1.w += v1.w;
    }
    float4* o = (float4*)(out + (size_t)t * DIM);
    o[tid * 2] = a0;
    o[tid * 2 + 1] = a1;
}

// ---------------- launch ----------------
extern "C" void kernel_launch(void* const* d_in, const int* in_sizes, int n_in,
                              void* d_out, int out_size) {
    const float* x  = (const float*)d_in[0];   // hidden_states [1,2048,2048]
    const float* gw = (const float*)d_in[1];   // gate_w  [64,2048]
    const float* wg = (const float*)d_in[2];   // w_gate  [64,768,2048]
    const float* wu = (const float*)d_in[3];   // w_up    [64,768,2048]
    const float* wd = (const float*)d_in[4];   // w_down  [64,2048,768]
    float* out = (float*)d_out;

    cudaFuncSetAttribute(k_ffn1_mma, cudaFuncAttributeMaxDynamicSharedMemorySize, SMEM_BYTES);
    cudaFuncSetAttribute(k_ffn2_mma, cudaFuncAttributeMaxDynamicSharedMemorySize, SMEM_BYTES);

    k_zero_counts<<<1, 64>>>();
    k_xsplit<<<(NTOK * DIM) / (256 * 8), 256>>>(x);
    k_gating<<<NTOK, 128>>>(x, gw);
    k_ffn1_mma<<<dim3(FFN / 128, CAP / 128, NEXP), 256, SMEM_BYTES>>>(wg, wu);
    k_ffn2_mma<<<dim3(DIM / 256, CAP / 128, NEXP), 256, SMEM_BYTES>>>(wd);
    k_combine<<<NTOK, 256>>>(out);
}